// round 9
// baseline (speedup 1.0000x reference)
#include <cuda_runtime.h>
#include <math.h>
#include <stdint.h>

#define T_LEN  2048
#define B_SZ   32
#define IN_SZ  256
#define H_SZ   512
#define OUT_SZ 256
#define DT_C   0.1f

#define RGROUPS 32
#define BGROUPS 4
#define NCTA    128
#define RPC     16
#define OPC     8
#define BPC     8
#define NTHR    256

// Pitches (floats), %4==0 and ==4 (mod 32)
#define P0  772
#define P1  1028
#define POW 516
#define PAX 260    // sA: x only (256 used)
#define PBB 1028   // sB: 512 h0 | 512 h1

#define SMEM_FLOATS (RPC*P0 + RPC*P1 + OPC*POW + BPC*PAX + BPC*PBB + 4224 + 4160 + 72)
#define SMEM_BYTES  (SMEM_FLOATS * 4)

typedef unsigned long long ull;

__device__ float g_h0[2][B_SZ][H_SZ];
__device__ float g_h1[2][B_SZ][H_SZ];
__device__ __align__(128) unsigned g_flag[BGROUPS][32];

__global__ void init_state_kernel() {
    int i = blockIdx.x * blockDim.x + threadIdx.x;
    const int n = 2 * B_SZ * H_SZ;
    if (i < n) {
        ((float*)g_h0)[i] = 0.0f;
        ((float*)g_h1)[i] = 0.0f;
    }
    if (i < BGROUPS * 32) ((unsigned*)g_flag)[i] = 0u;
}

__device__ __forceinline__ void cpa16(uint32_t dst, const void* src) {
    asm volatile("cp.async.cg.shared.global [%0], [%1], 16;"
                 :: "r"(dst), "l"(src) : "memory");
}
#define CP_COMMIT() asm volatile("cp.async.commit_group;" ::: "memory")
#define CP_WAIT(n)  asm volatile("cp.async.wait_group %0;" :: "n"(n) : "memory")

template<int PIT, int COFF>
__device__ __forceinline__ void stage_h(uint32_t ubase, const float* __restrict__ g,
                                        int b0, int bb, int c) {
#pragma unroll
    for (int q = 0; q < 4; q++) {
        cpa16(ubase + (bb * PIT + COFF + c + q * 128) * 4,
              &g[(size_t)(b0 + bb) * H_SZ + c + q * 128]);
    }
}

// --- pod barrier: per-CTA flag slots in one 128B line ---
__device__ __forceinline__ void pod_arrive(unsigned* flg, int rg, unsigned ph) {
    if (threadIdx.x == 0) {
        __threadfence();   // release: orders all block threads' prior STGs
        asm volatile("st.relaxed.gpu.global.u32 [%0], %1;"
                     :: "l"(flg + rg), "r"(ph) : "memory");
    }
}
// all-warp spin: every warp polls the 32 flags and self-releases (acquire).
__device__ __forceinline__ void pod_spin_all(const unsigned* flg, unsigned ph) {
    const int ln = threadIdx.x & 31;
    unsigned v;
    do {
        asm volatile("ld.acquire.gpu.global.u32 %0, [%1];"
                     : "=r"(v) : "l"(flg + ln) : "memory");
    } while (__any_sync(0xffffffffu, v < ph));
}

// packed dual-fp32 FMA (FFMA2)
__device__ __forceinline__ void fmax2(ull& d, ull a, ull b) {
    asm("fma.rn.f32x2 %0, %1, %2, %0;" : "+l"(d) : "l"(a), "l"(b));
}
__device__ __forceinline__ float x2sum(ull v) {
    float lo, hi;
    asm("mov.b64 {%0,%1}, %2;" : "=f"(lo), "=f"(hi) : "l"(v));
    return lo + hi;
}

template<int NIT, int KSTEP, int PW, int PAcc>
__device__ __forceinline__ void mm44p2(const float* __restrict__ sW, int rbase, int wk,
                                       const float* __restrict__ sAct, int bbase, int ak,
                                       ull acc[4][4]) {
#pragma unroll
    for (int it = 0; it < NIT; ++it) {
        ulonglong2 w[4], a[4];
#pragma unroll
        for (int i = 0; i < 4; i++)
            w[i] = *(const ulonglong2*)(sW + (rbase + i) * PW + wk + it * KSTEP);
#pragma unroll
        for (int j = 0; j < 4; j++)
            a[j] = *(const ulonglong2*)(sAct + (bbase + j) * PAcc + ak + it * KSTEP);
#pragma unroll
        for (int i = 0; i < 4; i++)
#pragma unroll
            for (int j = 0; j < 4; j++) {
                fmax2(acc[i][j], w[i].x, a[j].x);
                fmax2(acc[i][j], w[i].y, a[j].y);
            }
    }
}

__device__ __forceinline__ float sum32(const float* p) {
    float s0 = 0.f, s1 = 0.f, s2 = 0.f, s3 = 0.f;
#pragma unroll
    for (int kk = 0; kk < 32; kk += 4) {
        s0 += p[kk]; s1 += p[kk + 1]; s2 += p[kk + 2]; s3 += p[kk + 3];
    }
    return (s0 + s1) + (s2 + s3);
}
__device__ __forceinline__ float sum64(const float* p) {
    float s0 = 0.f, s1 = 0.f, s2 = 0.f, s3 = 0.f;
#pragma unroll
    for (int kk = 0; kk < 64; kk += 4) {
        s0 += p[kk]; s1 += p[kk + 1]; s2 += p[kk + 2]; s3 += p[kk + 3];
    }
    return (s0 + s1) + (s2 + s3);
}

__global__ void __launch_bounds__(NTHR, 1)
rnn_persistent(const float* __restrict__ x,
               const float* __restrict__ Win0, const float* __restrict__ bin0,
               const float* __restrict__ Wrec0, const float* __restrict__ tau0,
               const float* __restrict__ Win1, const float* __restrict__ bin1,
               const float* __restrict__ Wrec1, const float* __restrict__ tau1,
               const float* __restrict__ Wout, const float* __restrict__ bout,
               float* __restrict__ out)
{
    extern __shared__ float sm[];
    float* sW0   = sm;                   // [16][P0]
    float* sW1   = sW0 + RPC * P0;       // [16][P1]
    float* sWo   = sW1 + RPC * P1;       // [8][POW]
    float* sA    = sWo + OPC * POW;      // [8][PAX]  x(t)
    float* sB    = sA  + BPC * PAX;      // [8][PBB]  h0 | h1
    float* sRedA = sB  + BPC * PBB;      // 128*33
    float* sRedC = sRedA + 4224;         // 64*65
    float* sBi0  = sRedC + 4160;
    float* sIT0  = sBi0 + RPC;
    float* sBi1  = sIT0 + RPC;
    float* sIT1  = sBi1 + RPC;
    float* sBo   = sIT1 + RPC;

    const int tid = threadIdx.x;
    const int rg  = blockIdx.x & (RGROUPS - 1);
    const int bg  = blockIdx.x >> 5;
    const int b0  = bg * BPC;
    const int r0  = rg * RPC;
    const int o0  = rg * OPC;
    unsigned* flg = g_flag[bg];

    const uint32_t uA = (uint32_t)__cvta_generic_to_shared(sA);
    const uint32_t uB = (uint32_t)__cvta_generic_to_shared(sB);

    const int st_bb = tid >> 5;            // 0..7
    const int st_c  = (tid & 31) * 4;      // 0..124

    // ---- Prologue staging: x(0)->sA, h0(-1)->sB[0:512], h1(-1)->sB[512:] ----
    cpa16(uA + (st_bb * PAX + st_c) * 4,
          &x[((size_t)(b0 + st_bb) * T_LEN + 0) * IN_SZ + st_c]);
    cpa16(uA + (st_bb * PAX + st_c + 128) * 4,
          &x[((size_t)(b0 + st_bb) * T_LEN + 0) * IN_SZ + st_c + 128]);
    stage_h<PBB, 0>(uB, &g_h0[0][0][0], b0, st_bb, st_c);
    stage_h<PBB, 512>(uB, &g_h1[0][0][0], b0, st_bb, st_c);
    CP_COMMIT();

    // ---- Weights into SMEM (once) ----
    for (int idx = tid; idx < RPC * 768; idx += NTHR) {
        int r = idx / 768, c = idx % 768;
        float v = (c < IN_SZ) ? Win0[(r0 + r) * IN_SZ + c]
                              : Wrec0[(r0 + r) * H_SZ + (c - IN_SZ)];
        sW0[r * P0 + c] = v;
    }
    for (int idx = tid; idx < RPC * 1024; idx += NTHR) {
        int r = idx >> 10, c = idx & 1023;
        float v = (c < H_SZ) ? Win1[(r0 + r) * H_SZ + c]
                             : Wrec1[(r0 + r) * H_SZ + (c - H_SZ)];
        sW1[r * P1 + c] = v;
    }
    for (int idx = tid; idx < OPC * H_SZ; idx += NTHR) {
        int r = idx >> 9, c = idx & 511;
        sWo[r * POW + c] = Wout[(o0 + r) * H_SZ + c];
    }
    if (tid < RPC) {
        sBi0[tid] = bin0[r0 + tid];
        float tc = fminf(fmaxf(tau0[r0 + tid], 0.1f), 10.f);
        sIT0[tid] = DT_C / tc;
        sBi1[tid] = bin1[r0 + tid];
        tc = fminf(fmaxf(tau1[r0 + tid], 0.1f), 10.f);
        sIT1[tid] = DT_C / tc;
    }
    if (tid < OPC) sBo[tid] = bout[o0 + tid];

    // A/B decode
    const int rt    = tid & 3;
    const int bt    = (tid >> 2) & 1;
    const int ksl   = (tid >> 3) & 3;
    const int wrp   = tid >> 5;
    const int ksg   = wrp * 4 + ksl;
    const int rbase = rt * 4;
    const int bbase = bt * 4;
    const int kx = wrp * 32 + ksl * 4;   // A x-part (256)
    const int kh = wrp * 64 + ksl * 4;   // h-halves (512)
    // C decode
    const int rtC = tid & 1, btC = (tid >> 1) & 1;
    const int ksgC = tid >> 2;
    const int kbC = wrp * 64 + ((tid >> 2) & 7) * 4;

    // ---- Prologue compute: A(0) GEMM ----
    CP_WAIT(0);
    __syncthreads();
    {
        ull acc[4][4] = {};
        mm44p2<2, 16, P0, PAX>(sW0, rbase, kx, sA, bbase, kx, acc);
        mm44p2<4, 16, P0, PBB>(sW0, rbase, 256 + kh, sB, bbase, kh, acc);
#pragma unroll
        for (int i = 0; i < 4; i++)
#pragma unroll
            for (int j = 0; j < 4; j++)
                sRedA[(64 * bt + 16 * j + 4 * rt + i) * 33 + ksg] = x2sum(acc[i][j]);
    }

    for (int t = 0; t < T_LEN; t++) {
        const int pw = (t & 1) ^ 1;
        const unsigned ph1 = (unsigned)(2 * t + 1);
        const unsigned ph2 = (unsigned)(2 * t + 2);

        // (1) join: A(t) partials in sRedA visible; sA free for overwrite
        __syncthreads();

        // (2) prefetch x(t+1) -> sA (oldest pending group after h1's)
        if (t + 1 < T_LEN) {
            cpa16(uA + (st_bb * PAX + st_c) * 4,
                  &x[((size_t)(b0 + st_bb) * T_LEN + (t + 1)) * IN_SZ + st_c]);
            cpa16(uA + (st_bb * PAX + st_c + 128) * 4,
                  &x[((size_t)(b0 + st_bb) * T_LEN + (t + 1)) * IN_SZ + st_c + 128]);
        }
        CP_COMMIT();

        // (3) A-reduce -> h0(t)   (reads sRedA + own h0(t-1) slice in sB)
        if (tid < 128) {
            float sum = sum32(&sRedA[tid * 33]) + sBi0[tid & 15];
            float tgt = tanhf(sum);
            float hold = sB[(tid >> 4) * PBB + r0 + (tid & 15)];
            g_h0[pw][b0 + (tid >> 4)][r0 + (tid & 15)] = hold + (tgt - hold) * sIT0[tid & 15];
        }
        __syncthreads();
        pod_arrive(flg, rg, ph1);                       // bar1 arrive (early)

        // (4) drain h1(t-1) group (was hidden under A-reduce); join
        CP_WAIT(1);                                     // h1 done; x(t+1) may fly
        __syncthreads();

        // (5) bar1 window: B1 GEMM (h1(t-1) half) + C(t-1) GEMM
        ull accB[4][4] = {};
        mm44p2<4, 16, P1, PBB>(sW1, rbase, 512 + kh, sB, bbase, 512 + kh, accB);
        if (t) {
            ull accC[4][4] = {};
            mm44p2<2, 32, POW, PBB>(sWo, rtC * 4, kbC, sB, btC * 4, 512 + kbC, accC);
#pragma unroll
            for (int i = 0; i < 4; i++)
#pragma unroll
                for (int j = 0; j < 4; j++)
                    sRedC[(32 * btC + 8 * j + 4 * rtC + i) * 65 + ksgC] = x2sum(accC[i][j]);
        }
        __syncthreads();                                // sRedC visible

        // (6) bar1 spin (all warps self-release with acquire)
        pod_spin_all(flg, ph1);

        // (7) stage h0(t) -> sB[0:512]; emit out(t-1) while the fetch flies
        stage_h<PBB, 0>(uB, &g_h0[pw][0][0], b0, st_bb, st_c);
        CP_COMMIT();
        if (t && tid >= 128 && tid < 192) {
            const int rw = tid - 128;
            const int cb = rw >> 3, co = rw & 7;
            float res = __ldg(&x[((size_t)(b0 + cb) * T_LEN + (t - 1)) * IN_SZ + o0 + co]);
            out[((size_t)(b0 + cb) * T_LEN + (t - 1)) * OUT_SZ + o0 + co]
                = sum64(&sRedC[rw * 65]) + sBo[co] + res;
        }
        CP_WAIT(0);                                     // x(t+1) + h0(t) done (own)
        __syncthreads();                                // -> ALL threads' copies done

        // (8) B2 GEMM (h0(t) half), same accumulators
        mm44p2<4, 16, P1, PBB>(sW1, rbase, kh, sB, bbase, kh, accB);
#pragma unroll
        for (int i = 0; i < 4; i++)
#pragma unroll
            for (int j = 0; j < 4; j++)
                sRedA[(64 * bt + 16 * j + 4 * rt + i) * 33 + ksg] = x2sum(accB[i][j]);
        __syncthreads();

        // (9) B-reduce -> h1(t)
        if (tid < 128) {
            float sum = sum32(&sRedA[tid * 33]) + sBi1[tid & 15];
            float tgt = tanhf(sum);
            float hold = sB[(tid >> 4) * PBB + 512 + r0 + (tid & 15)];
            g_h1[pw][b0 + (tid >> 4)][r0 + (tid & 15)] = hold + (tgt - hold) * sIT1[tid & 15];
        }
        __syncthreads();
        pod_arrive(flg, rg, ph2);                       // bar2 arrive (early)

        // (10) bar2 window: A(t+1) GEMM (x(t+1) + h0(t) already joined at (7))
        if (t + 1 < T_LEN) {
            ull accA[4][4] = {};
            mm44p2<2, 16, P0, PAX>(sW0, rbase, kx, sA, bbase, kx, accA);
            mm44p2<4, 16, P0, PBB>(sW0, rbase, 256 + kh, sB, bbase, kh, accA);
#pragma unroll
            for (int i = 0; i < 4; i++)
#pragma unroll
                for (int j = 0; j < 4; j++)
                    sRedA[(64 * bt + 16 * j + 4 * rt + i) * 33 + ksg] = x2sum(accA[i][j]);
        }

        // (11) bar2 spin; stage h1(t) -> sB[512:] (consumed next iter after (4))
        pod_spin_all(flg, ph2);
        stage_h<PBB, 512>(uB, &g_h1[pw][0][0], b0, st_bb, st_c);
        CP_COMMIT();
    }

    // ===== Epilogue: out(T-1) =====
    CP_WAIT(0);
    __syncthreads();
    {
        ull accC[4][4] = {};
        mm44p2<2, 32, POW, PBB>(sWo, rtC * 4, kbC, sB, btC * 4, 512 + kbC, accC);
#pragma unroll
        for (int i = 0; i < 4; i++)
#pragma unroll
            for (int j = 0; j < 4; j++)
                sRedC[(32 * btC + 8 * j + 4 * rtC + i) * 65 + ksgC] = x2sum(accC[i][j]);
    }
    __syncthreads();
    if (tid < 64) {
        const int eb = tid >> 3, eo = tid & 7;
        float res = __ldg(&x[((size_t)(b0 + eb) * T_LEN + (T_LEN - 1)) * IN_SZ + o0 + eo]);
        out[((size_t)(b0 + eb) * T_LEN + (T_LEN - 1)) * OUT_SZ + o0 + eo]
            = sum64(&sRedC[tid * 65]) + sBo[eo] + res;
    }
}

extern "C" void kernel_launch(void* const* d_in, const int* in_sizes, int n_in,
                              void* d_out, int out_size) {
    const float* x     = (const float*)d_in[0];
    const float* Win0  = (const float*)d_in[1];
    const float* bin0  = (const float*)d_in[2];
    const float* Wrec0 = (const float*)d_in[3];
    const float* tau0  = (const float*)d_in[4];
    const float* Win1  = (const float*)d_in[5];
    const float* bin1  = (const float*)d_in[6];
    const float* Wrec1 = (const float*)d_in[7];
    const float* tau1  = (const float*)d_in[8];
    const float* Wout  = (const float*)d_in[9];
    const float* bout  = (const float*)d_in[10];
    float* outp        = (float*)d_out;

    cudaFuncSetAttribute(rnn_persistent,
                         cudaFuncAttributeMaxDynamicSharedMemorySize, SMEM_BYTES);

    init_state_kernel<<<128, 256>>>();
    rnn_persistent<<<NCTA, NTHR, SMEM_BYTES>>>(x, Win0, bin0, Wrec0, tau0,
                                               Win1, bin1, Wrec1, tau1,
                                               Wout, bout, outp);
}

// round 10
// speedup vs baseline: 1.1848x; 1.1848x over previous
#include <cuda_runtime.h>
#include <math.h>
#include <stdint.h>

#define T_LEN  2048
#define B_SZ   32
#define IN_SZ  256
#define H_SZ   512
#define OUT_SZ 256
#define DT_C   0.1f

#define RGROUPS 32
#define BGROUPS 4
#define NCTA    128
#define RPC     16
#define OPC     8
#define BPC     8
#define NTHR    256

// Pitches (floats), %4==0 and ==4 (mod 32)
#define P0  772
#define P1  1028
#define POW 516
#define PX  260    // sX: x(t), 256 used
#define PH  1028   // sH: 512 h0 | 512 h1

#define SMEM_FLOATS (RPC*P0 + RPC*P1 + OPC*POW + BPC*PX + BPC*PH + 4224 + 4224 + 72)
#define SMEM_BYTES  (SMEM_FLOATS * 4)

typedef unsigned long long ull;

__device__ float g_h0[2][B_SZ][H_SZ];
__device__ float g_h1[2][B_SZ][H_SZ];
__device__ __align__(128) unsigned g_flag[BGROUPS][32];

__global__ void init_state_kernel() {
    int i = blockIdx.x * blockDim.x + threadIdx.x;
    const int n = 2 * B_SZ * H_SZ;
    if (i < n) {
        ((float*)g_h0)[i] = 0.0f;
        ((float*)g_h1)[i] = 0.0f;
    }
    if (i < BGROUPS * 32) ((unsigned*)g_flag)[i] = 0u;
}

__device__ __forceinline__ void cpa16(uint32_t dst, const void* src) {
    asm volatile("cp.async.cg.shared.global [%0], [%1], 16;"
                 :: "r"(dst), "l"(src) : "memory");
}
#define CP_COMMIT() asm volatile("cp.async.commit_group;" ::: "memory")
#define CP_WAIT(n)  asm volatile("cp.async.wait_group %0;" :: "n"(n) : "memory")

template<int PIT, int COFF>
__device__ __forceinline__ void stage_h(uint32_t ubase, const float* __restrict__ g,
                                        int b0, int bb, int c) {
#pragma unroll
    for (int q = 0; q < 4; q++) {
        cpa16(ubase + (bb * PIT + COFF + c + q * 128) * 4,
              &g[(size_t)(b0 + bb) * H_SZ + c + q * 128]);
    }
}

// --- pod barrier: per-CTA flag slots; warp0 spins, block joins via sync ---
__device__ __forceinline__ void pod_arrive(unsigned* flg, int rg, unsigned ph) {
    if (threadIdx.x == 0) {
        __threadfence();   // release: orders all block threads' prior STGs
        asm volatile("st.relaxed.gpu.global.u32 [%0], %1;"
                     :: "l"(flg + rg), "r"(ph) : "memory");
    }
}
__device__ __forceinline__ void pod_spin_w0(const unsigned* flg, unsigned ph) {
    if (threadIdx.x < 32) {
        unsigned v;
        do {
            asm volatile("ld.acquire.gpu.global.u32 %0, [%1];"
                         : "=r"(v) : "l"(flg + threadIdx.x) : "memory");
        } while (__any_sync(0xffffffffu, v < ph));
    }
}

// packed dual-fp32 FMA (FFMA2)
__device__ __forceinline__ void fmax2(ull& d, ull a, ull b) {
    asm("fma.rn.f32x2 %0, %1, %2, %0;" : "+l"(d) : "l"(a), "l"(b));
}
__device__ __forceinline__ float x2sum(ull v) {
    float lo, hi;
    asm("mov.b64 {%0,%1}, %2;" : "=f"(lo), "=f"(hi) : "l"(v));
    return lo + hi;
}

template<int NIT, int KSTEP, int PW, int PAcc>
__device__ __forceinline__ void mm44p2(const float* __restrict__ sW, int rbase, int wk,
                                       const float* __restrict__ sAct, int bbase, int ak,
                                       ull acc[4][4]) {
#pragma unroll
    for (int it = 0; it < NIT; ++it) {
        ulonglong2 w[4], a[4];
#pragma unroll
        for (int i = 0; i < 4; i++)
            w[i] = *(const ulonglong2*)(sW + (rbase + i) * PW + wk + it * KSTEP);
#pragma unroll
        for (int j = 0; j < 4; j++)
            a[j] = *(const ulonglong2*)(sAct + (bbase + j) * PAcc + ak + it * KSTEP);
#pragma unroll
        for (int i = 0; i < 4; i++)
#pragma unroll
            for (int j = 0; j < 4; j++) {
                fmax2(acc[i][j], w[i].x, a[j].x);
                fmax2(acc[i][j], w[i].y, a[j].y);
            }
    }
}

__device__ __forceinline__ float sum32(const float* p) {
    float s0 = 0.f, s1 = 0.f, s2 = 0.f, s3 = 0.f;
#pragma unroll
    for (int kk = 0; kk < 32; kk += 4) {
        s0 += p[kk]; s1 += p[kk + 1]; s2 += p[kk + 2]; s3 += p[kk + 3];
    }
    return (s0 + s1) + (s2 + s3);
}
__device__ __forceinline__ float sum64(const float* p) {
    float s0 = 0.f, s1 = 0.f, s2 = 0.f, s3 = 0.f;
#pragma unroll
    for (int kk = 0; kk < 64; kk += 4) {
        s0 += p[kk]; s1 += p[kk + 1]; s2 += p[kk + 2]; s3 += p[kk + 3];
    }
    return (s0 + s1) + (s2 + s3);
}

__global__ void __launch_bounds__(NTHR, 1)
rnn_persistent(const float* __restrict__ x,
               const float* __restrict__ Win0, const float* __restrict__ bin0,
               const float* __restrict__ Wrec0, const float* __restrict__ tau0,
               const float* __restrict__ Win1, const float* __restrict__ bin1,
               const float* __restrict__ Wrec1, const float* __restrict__ tau1,
               const float* __restrict__ Wout, const float* __restrict__ bout,
               float* __restrict__ out)
{
    extern __shared__ float sm[];
    float* sW0   = sm;                   // [16][P0]
    float* sW1   = sW0 + RPC * P0;       // [16][P1]
    float* sWo   = sW1 + RPC * P1;       // [8][POW]
    float* sX    = sWo + OPC * POW;      // [8][PX]   x(t)
    float* sH    = sX  + BPC * PX;       // [8][PH]   h0(t-1) | h1(t-2)
    float* sRedA = sH  + BPC * PH;       // 128*33 = 4224   (A partials)
    float* sRedB = sRedA + 4224;         // 128*33 = 4224   (B partials; C reuses)
    float* sRedC = sRedB;                // 64*65 = 4160 (within sRedB area)
    float* sBi0  = sRedB + 4224;
    float* sIT0  = sBi0 + RPC;
    float* sBi1  = sIT0 + RPC;
    float* sIT1  = sBi1 + RPC;
    float* sBo   = sIT1 + RPC;

    const int tid = threadIdx.x;
    const int rg  = blockIdx.x & (RGROUPS - 1);
    const int bg  = blockIdx.x >> 5;
    const int b0  = bg * BPC;
    const int r0  = rg * RPC;
    const int o0  = rg * OPC;
    unsigned* flg = g_flag[bg];

    const uint32_t uX = (uint32_t)__cvta_generic_to_shared(sX);
    const uint32_t uH = (uint32_t)__cvta_generic_to_shared(sH);

    const int st_bb = tid >> 5;            // 0..7
    const int st_c  = (tid & 31) * 4;      // 0..124

    // ---- Prologue staging: x(0) [group X], h0(-1)|h1(-1) zeros [group H] ----
    cpa16(uX + (st_bb * PX + st_c) * 4,
          &x[((size_t)(b0 + st_bb) * T_LEN + 0) * IN_SZ + st_c]);
    cpa16(uX + (st_bb * PX + st_c + 128) * 4,
          &x[((size_t)(b0 + st_bb) * T_LEN + 0) * IN_SZ + st_c + 128]);
    CP_COMMIT();
    stage_h<PH, 0>(uH, &g_h0[1][0][0], b0, st_bb, st_c);    // zeros
    stage_h<PH, 512>(uH, &g_h1[1][0][0], b0, st_bb, st_c);  // zeros
    CP_COMMIT();

    // ---- Weights into SMEM (once) ----
    for (int idx = tid; idx < RPC * 768; idx += NTHR) {
        int r = idx / 768, c = idx % 768;
        float v = (c < IN_SZ) ? Win0[(r0 + r) * IN_SZ + c]
                              : Wrec0[(r0 + r) * H_SZ + (c - IN_SZ)];
        sW0[r * P0 + c] = v;
    }
    for (int idx = tid; idx < RPC * 1024; idx += NTHR) {
        int r = idx >> 10, c = idx & 1023;
        float v = (c < H_SZ) ? Win1[(r0 + r) * H_SZ + c]
                             : Wrec1[(r0 + r) * H_SZ + (c - H_SZ)];
        sW1[r * P1 + c] = v;
    }
    for (int idx = tid; idx < OPC * H_SZ; idx += NTHR) {
        int r = idx >> 9, c = idx & 511;
        sWo[r * POW + c] = Wout[(o0 + r) * H_SZ + c];
    }
    if (tid < RPC) {
        sBi0[tid] = bin0[r0 + tid];
        float tc = fminf(fmaxf(tau0[r0 + tid], 0.1f), 10.f);
        sIT0[tid] = DT_C / tc;
        sBi1[tid] = bin1[r0 + tid];
        tc = fminf(fmaxf(tau1[r0 + tid], 0.1f), 10.f);
        sIT1[tid] = DT_C / tc;
    }
    if (tid < OPC) sBo[tid] = bout[o0 + tid];

    // A/B decode
    const int rt    = tid & 3;
    const int bt    = (tid >> 2) & 1;
    const int ksl   = (tid >> 3) & 3;
    const int wrp   = tid >> 5;
    const int ksg   = wrp * 4 + ksl;
    const int rbase = rt * 4;
    const int bbase = bt * 4;
    const int kx = wrp * 32 + ksl * 4;   // x-part (256)
    const int kh = wrp * 64 + ksl * 4;   // h-halves (512)
    // C decode
    const int rtC = tid & 1, btC = (tid >> 1) & 1;
    const int ksgC = tid >> 2;
    const int kbC = wrp * 64 + ((tid >> 2) & 7) * 4;

    // ===================== main loop: one barrier per step ====================
    // step t computes: A(t) -> h0(t),  B(t-1) -> h1(t-1),  C(t-2) -> out(t-2)
    for (int t = 0; t < T_LEN; t++) {
        const int s0i = t & 1;          // g_h0 slot for h0(t)
        const int s1i = s0i ^ 1;        // g_h1 slot for h1(t-1)

        // (1) x(t) group landed
        CP_WAIT(1);
        __syncthreads();

        // (2) A-x GEMM while h group may still fly
        ull accA[4][4] = {};
        mm44p2<2, 16, P0, PX>(sW0, rbase, kx, sX, bbase, kx, accA);

        // (3) h0(t-1)|h1(t-2) landed
        CP_WAIT(0);
        __syncthreads();

        // (4) A-h GEMM; store A partials
        mm44p2<4, 16, P0, PH>(sW0, rbase, 256 + kh, sH, bbase, kh, accA);
#pragma unroll
        for (int i = 0; i < 4; i++)
#pragma unroll
            for (int j = 0; j < 4; j++)
                sRedA[(64 * bt + 16 * j + 4 * rt + i) * 33 + ksg] = x2sum(accA[i][j]);
        __syncthreads();

        // (5) A-reduce (tid<128) -> g_h0[s0i]; all threads then B GEMM
        if (tid < 128) {
            float sum = sum32(&sRedA[tid * 33]) + sBi0[tid & 15];
            float tgt = tanhf(sum);
            float hold = sH[(tid >> 4) * PH + r0 + (tid & 15)];        // h0(t-1)
            g_h0[s0i][b0 + (tid >> 4)][r0 + (tid & 15)] = hold + (tgt - hold) * sIT0[tid & 15];
        }
        // (6) B(t-1) GEMM (h0(t-1) + h1(t-2)) -> sRedB (distinct from sRedA)
        {
            ull accB[4][4] = {};
            mm44p2<4, 16, P1, PH>(sW1, rbase, kh, sH, bbase, kh, accB);
            mm44p2<4, 16, P1, PH>(sW1, rbase, 512 + kh, sH, bbase, 512 + kh, accB);
#pragma unroll
            for (int i = 0; i < 4; i++)
#pragma unroll
                for (int j = 0; j < 4; j++)
                    sRedB[(64 * bt + 16 * j + 4 * rt + i) * 33 + ksg] = x2sum(accB[i][j]);
        }
        __syncthreads();

        // (7) B-reduce -> g_h1[s1i]  (skip t=0: B(-1) is garbage; keep slot zeros)
        if (t && tid < 128) {
            float sum = sum32(&sRedB[tid * 33]) + sBi1[tid & 15];
            float tgt = tanhf(sum);
            float hold = sH[(tid >> 4) * PH + 512 + r0 + (tid & 15)];  // h1(t-2)
            g_h1[s1i][b0 + (tid >> 4)][r0 + (tid & 15)] = hold + (tgt - hold) * sIT1[tid & 15];
        }
        __syncthreads();
        pod_arrive(flg, rg, (unsigned)(t + 1));          // publish h0(t), h1(t-1)

        // (8) barrier window: C(t-2) GEMM (h1(t-2) still in sH)
        if (t >= 2) {
            ull accC[4][4] = {};
            mm44p2<2, 32, POW, PH>(sWo, rtC * 4, kbC, sH, btC * 4, 512 + kbC, accC);
#pragma unroll
            for (int i = 0; i < 4; i++)
#pragma unroll
                for (int j = 0; j < 4; j++)
                    sRedC[(32 * btC + 8 * j + 4 * rtC + i) * 65 + ksgC] = x2sum(accC[i][j]);
        }
        __syncthreads();                                 // sRedC visible

        // (9) warps 4-5 emit out(t-2) while warp0 spins
        if (t >= 2 && tid >= 128 && tid < 192) {
            const int rw = tid - 128;
            const int cb = rw >> 3, co = rw & 7;
            float res = __ldg(&x[((size_t)(b0 + cb) * T_LEN + (t - 2)) * IN_SZ + o0 + co]);
            out[((size_t)(b0 + cb) * T_LEN + (t - 2)) * OUT_SZ + o0 + co]
                = sum64(&sRedC[rw * 65]) + sBo[co] + res;
        }
        pod_spin_w0(flg, (unsigned)(t + 1));
        __syncthreads();

        // (10) stage next step's data: x(t+1) [group X], h0(t)|h1(t-1) [group H]
        if (t + 1 < T_LEN) {
            cpa16(uX + (st_bb * PX + st_c) * 4,
                  &x[((size_t)(b0 + st_bb) * T_LEN + (t + 1)) * IN_SZ + st_c]);
            cpa16(uX + (st_bb * PX + st_c + 128) * 4,
                  &x[((size_t)(b0 + st_bb) * T_LEN + (t + 1)) * IN_SZ + st_c + 128]);
        }
        CP_COMMIT();                                     // group X (may be empty)
        stage_h<PH, 0>(uH, &g_h0[s0i][0][0], b0, st_bb, st_c);
        stage_h<PH, 512>(uH, &g_h1[s1i][0][0], b0, st_bb, st_c);
        CP_COMMIT();                                     // group H
    }

    // ===== Epilogue: B(T-1) -> h1(T-1); C(T-2); C(T-1) =====
    CP_WAIT(0);
    __syncthreads();                                     // h0(T-1), h1(T-2) in sH
    {
        ull accB[4][4] = {};
        mm44p2<4, 16, P1, PH>(sW1, rbase, kh, sH, bbase, kh, accB);
        mm44p2<4, 16, P1, PH>(sW1, rbase, 512 + kh, sH, bbase, 512 + kh, accB);
#pragma unroll
        for (int i = 0; i < 4; i++)
#pragma unroll
            for (int j = 0; j < 4; j++)
                sRedA[(64 * bt + 16 * j + 4 * rt + i) * 33 + ksg] = x2sum(accB[i][j]);
    }
    __syncthreads();
    if (tid < 128) {
        float sum = sum32(&sRedA[tid * 33]) + sBi1[tid & 15];
        float tgt = tanhf(sum);
        float hold = sH[(tid >> 4) * PH + 512 + r0 + (tid & 15)];      // h1(T-2)
        g_h1[(T_LEN - 1) & 1][b0 + (tid >> 4)][r0 + (tid & 15)] = hold + (tgt - hold) * sIT1[tid & 15];
    }
    __syncthreads();
    pod_arrive(flg, rg, (unsigned)(T_LEN + 1));

    // C(T-2) in window
    {
        ull accC[4][4] = {};
        mm44p2<2, 32, POW, PH>(sWo, rtC * 4, kbC, sH, btC * 4, 512 + kbC, accC);
#pragma unroll
        for (int i = 0; i < 4; i++)
#pragma unroll
            for (int j = 0; j < 4; j++)
                sRedC[(32 * btC + 8 * j + 4 * rtC + i) * 65 + ksgC] = x2sum(accC[i][j]);
    }
    __syncthreads();
    if (tid >= 128 && tid < 192) {
        const int rw = tid - 128;
        const int cb = rw >> 3, co = rw & 7;
        float res = __ldg(&x[((size_t)(b0 + cb) * T_LEN + (T_LEN - 2)) * IN_SZ + o0 + co]);
        out[((size_t)(b0 + cb) * T_LEN + (T_LEN - 2)) * OUT_SZ + o0 + co]
            = sum64(&sRedC[rw * 65]) + sBo[co] + res;
    }
    pod_spin_w0(flg, (unsigned)(T_LEN + 1));
    __syncthreads();

    // stage h1(T-1); C(T-1)
    stage_h<PH, 512>(uH, &g_h1[(T_LEN - 1) & 1][0][0], b0, st_bb, st_c);
    CP_COMMIT();
    CP_WAIT(0);
    __syncthreads();
    {
        ull accC[4][4] = {};
        mm44p2<2, 32, POW, PH>(sWo, rtC * 4, kbC, sH, btC * 4, 512 + kbC, accC);
#pragma unroll
        for (int i = 0; i < 4; i++)
#pragma unroll
            for (int j = 0; j < 4; j++)
                sRedC[(32 * btC + 8 * j + 4 * rtC + i) * 65 + ksgC] = x2sum(accC[i][j]);
    }
    __syncthreads();
    if (tid < 64) {
        const int eb = tid >> 3, eo = tid & 7;
        float res = __ldg(&x[((size_t)(b0 + eb) * T_LEN + (T_LEN - 1)) * IN_SZ + o0 + eo]);
        out[((size_t)(b0 + eb) * T_LEN + (T_LEN - 1)) * OUT_SZ + o0 + eo]
            = sum64(&sRedC[tid * 65]) + sBo[eo] + res;
    }
}

extern "C" void kernel_launch(void* const* d_in, const int* in_sizes, int n_in,
                              void* d_out, int out_size) {
    const float* x     = (const float*)d_in[0];
    const float* Win0  = (const float*)d_in[1];
    const float* bin0  = (const float*)d_in[2];
    const float* Wrec0 = (const float*)d_in[3];
    const float* tau0  = (const float*)d_in[4];
    const float* Win1  = (const float*)d_in[5];
    const float* bin1  = (const float*)d_in[6];
    const float* Wrec1 = (const float*)d_in[7];
    const float* tau1  = (const float*)d_in[8];
    const float* Wout  = (const float*)d_in[9];
    const float* bout  = (const float*)d_in[10];
    float* outp        = (float*)d_out;

    cudaFuncSetAttribute(rnn_persistent,
                         cudaFuncAttributeMaxDynamicSharedMemorySize, SMEM_BYTES);

    init_state_kernel<<<128, 256>>>();
    rnn_persistent<<<NCTA, NTHR, SMEM_BYTES>>>(x, Win0, bin0, Wrec0, tau0,
                                               Win1, bin1, Wrec1, tau1,
                                               Wout, bout, outp);
}